// round 10
// baseline (speedup 1.0000x reference)
#include <cuda_runtime.h>

#define AA   64
#define TT   512
#define DD   256
#define HH   4
#define HDIM 64
#define AT   (AA*TT)
#define NSPL 2
#define AHT  (AA*HH*TT)

typedef unsigned long long ull;

// Scratch (allocation-free)
__device__ float g_q[AT*DD];
__device__ float g_k[AT*DD];
__device__ float g_v[AT*DD];
__device__ float g_ctx[AT*DD];
__device__ float g_pm[NSPL*AHT];          // partial max
__device__ float g_pl[NSPL*AHT];          // partial sum
__device__ float g_po[(size_t)NSPL*AHT*HDIM];   // partial (unnormalized) output

// ---------------------------------------------------------------------------
// f32x2 packed-math helpers
// ---------------------------------------------------------------------------
__device__ __forceinline__ ull dup2(float x) {
    ull r;
    asm("mov.b64 %0, {%1, %1};" : "=l"(r) : "r"(__float_as_uint(x)));
    return r;
}
__device__ __forceinline__ void fma2(ull &d, ull a, ull b) {
    asm("fma.rn.f32x2 %0, %1, %2, %0;" : "+l"(d) : "l"(a), "l"(b));
}
__device__ __forceinline__ ull mul2(ull a, ull b) {
    ull r;
    asm("mul.rn.f32x2 %0, %1, %2;" : "=l"(r) : "l"(a), "l"(b));
    return r;
}
__device__ __forceinline__ float2 unpack2(ull v) {
    float2 f;
    asm("mov.b64 {%0, %1}, %2;" : "=f"(f.x), "=f"(f.y) : "l"(v));
    return f;
}

// ---------------------------------------------------------------------------
// GEMM (exact R8): BM=BN=128, BK=16, double-buffered, FFMA2.
// ---------------------------------------------------------------------------
__device__ __forceinline__ void gemm_tile(
    const float (* __restrict__ Ak)[132], const float (* __restrict__ Bk)[132],
    int tx, int ty, ull acc[8][4])
{
    #pragma unroll
    for (int k = 0; k < 16; k++) {
        const float4     a0 = *(const float4*)&Ak[k][ty << 2];
        const float4     a1 = *(const float4*)&Ak[k][64 + (ty << 2)];
        const ulonglong2 b0 = *(const ulonglong2*)&Bk[k][tx << 2];
        const ulonglong2 b1 = *(const ulonglong2*)&Bk[k][64 + (tx << 2)];
        ull am[8] = { dup2(a0.x), dup2(a0.y), dup2(a0.z), dup2(a0.w),
                      dup2(a1.x), dup2(a1.y), dup2(a1.z), dup2(a1.w) };
        #pragma unroll
        for (int mi = 0; mi < 8; mi++) {
            fma2(acc[mi][0], am[mi], b0.x);
            fma2(acc[mi][1], am[mi], b0.y);
            fma2(acc[mi][2], am[mi], b1.x);
            fma2(acc[mi][3], am[mi], b1.y);
        }
    }
}

__device__ __forceinline__ void gemm_body(
    const float* __restrict__ X, const float* __restrict__ W,
    const float* __restrict__ bias, float* __restrict__ Y,
    int m0, int n0)
{
    __shared__ float As[2][16][132];
    __shared__ float Bs[2][16][132];

    const int tid = threadIdx.x;
    const int tx  = tid & 15;
    const int ty  = tid >> 4;
    const int lr  = tid >> 2;
    const int lc  = (tid & 3) << 2;

    ull acc[8][4];
    #pragma unroll
    for (int i = 0; i < 8; i++)
        #pragma unroll
        for (int j = 0; j < 4; j++) acc[i][j] = 0ull;

    const float* xp0 = &X[(size_t)(m0 + lr)      * DD + lc];
    const float* xp1 = &X[(size_t)(m0 + 64 + lr) * DD + lc];
    const float* wp0 = &W[(size_t)(n0 + lr)      * DD + lc];
    const float* wp1 = &W[(size_t)(n0 + 64 + lr) * DD + lc];

    {
        float4 x0 = *(const float4*)(xp0);
        float4 x1 = *(const float4*)(xp1);
        float4 w0 = *(const float4*)(wp0);
        float4 w1 = *(const float4*)(wp1);
        As[0][lc+0][lr] = x0.x; As[0][lc+1][lr] = x0.y; As[0][lc+2][lr] = x0.z; As[0][lc+3][lr] = x0.w;
        As[0][lc+0][64+lr] = x1.x; As[0][lc+1][64+lr] = x1.y; As[0][lc+2][64+lr] = x1.z; As[0][lc+3][64+lr] = x1.w;
        Bs[0][lc+0][lr] = w0.x; Bs[0][lc+1][lr] = w0.y; Bs[0][lc+2][lr] = w0.z; Bs[0][lc+3][lr] = w0.w;
        Bs[0][lc+0][64+lr] = w1.x; Bs[0][lc+1][64+lr] = w1.y; Bs[0][lc+2][64+lr] = w1.z; Bs[0][lc+3][64+lr] = w1.w;
    }
    __syncthreads();

    int p = 0;
    for (int k0 = 16; k0 < 256; k0 += 16) {
        float4 x0 = *(const float4*)(xp0 + k0);
        float4 x1 = *(const float4*)(xp1 + k0);
        float4 w0 = *(const float4*)(wp0 + k0);
        float4 w1 = *(const float4*)(wp1 + k0);

        gemm_tile(As[p], Bs[p], tx, ty, acc);

        const int q = p ^ 1;
        As[q][lc+0][lr] = x0.x; As[q][lc+1][lr] = x0.y; As[q][lc+2][lr] = x0.z; As[q][lc+3][lr] = x0.w;
        As[q][lc+0][64+lr] = x1.x; As[q][lc+1][64+lr] = x1.y; As[q][lc+2][64+lr] = x1.z; As[q][lc+3][64+lr] = x1.w;
        Bs[q][lc+0][lr] = w0.x; Bs[q][lc+1][lr] = w0.y; Bs[q][lc+2][lr] = w0.z; Bs[q][lc+3][lr] = w0.w;
        Bs[q][lc+0][64+lr] = w1.x; Bs[q][lc+1][64+lr] = w1.y; Bs[q][lc+2][64+lr] = w1.z; Bs[q][lc+3][64+lr] = w1.w;
        __syncthreads();
        p = q;
    }
    gemm_tile(As[p], Bs[p], tx, ty, acc);

    float4 bv0 = *(const float4*)&bias[n0 + (tx << 2)];
    float4 bv1 = *(const float4*)&bias[n0 + 64 + (tx << 2)];
    #pragma unroll
    for (int mi = 0; mi < 8; mi++) {
        const int m = m0 + ((mi < 4) ? ((ty << 2) + mi) : (64 + (ty << 2) + mi - 4));
        float2 p0 = unpack2(acc[mi][0]);
        float2 p1 = unpack2(acc[mi][1]);
        float4 r0 = { p0.x + bv0.x, p0.y + bv0.y, p1.x + bv0.z, p1.y + bv0.w };
        *(float4*)&Y[(size_t)m * DD + n0 + (tx << 2)] = r0;
        float2 p2 = unpack2(acc[mi][2]);
        float2 p3 = unpack2(acc[mi][3]);
        float4 r1 = { p2.x + bv1.x, p2.y + bv1.y, p3.x + bv1.z, p3.y + bv1.w };
        *(float4*)&Y[(size_t)m * DD + n0 + 64 + (tx << 2)] = r1;
    }
}

__global__ __launch_bounds__(256, 2) void gemm_qkv(
    const float* __restrict__ X,
    const float* __restrict__ Wq, const float* __restrict__ Wk, const float* __restrict__ Wv,
    const float* __restrict__ bq, const float* __restrict__ bk, const float* __restrict__ bv,
    float* __restrict__ Yq, float* __restrict__ Yk, float* __restrict__ Yv)
{
    const int z = blockIdx.z;
    const float* W = (z == 0) ? Wq : (z == 1) ? Wk : Wv;
    const float* b = (z == 0) ? bq : (z == 1) ? bk : bv;
    float*       Y = (z == 0) ? Yq : (z == 1) ? Yk : Yv;
    gemm_body(X, W, b, Y, blockIdx.x * 128, blockIdx.y * 128);
}

__global__ __launch_bounds__(256, 2) void gemm_single(
    const float* __restrict__ X, const float* __restrict__ W,
    const float* __restrict__ bias, float* __restrict__ Y)
{
    gemm_body(X, W, bias, Y, blockIdx.x * 128, blockIdx.y * 128);
}

// ---------------------------------------------------------------------------
// Banded sparse attention, SPLIT-K partials.  Compute core = exact R4.
// Each block: 32 queries of one (a,h), split s of NSPL over the chunk list.
// Writes unnormalized o + per-query (m, l) partials.
// ---------------------------------------------------------------------------
__global__ __launch_bounds__(256, 2) void attn_part(
    const float* __restrict__ pos,
    const int* __restrict__ p_md, const int* __restrict__ p_tw)
{
    __shared__ float Qs[32][68];
    __shared__ float Ks[32][68];
    __shared__ float Vs[32][68];

    const int a    = blockIdx.z;
    const int h    = blockIdx.y;
    const int s    = blockIdx.x & (NSPL - 1);
    const int q0   = (blockIdx.x >> 1) * 32;
    const int tid  = threadIdx.x;
    const int w    = tid >> 5;
    const int lane = tid & 31;
    const int w4   = w << 2;

    const int   tw  = *p_tw;
    const float mdf = (float)(*p_md);
    const float md2 = mdf * mdf;

    {
        const float* qbase = g_q + (size_t)(a*TT + q0) * DD + h*HDIM;
        #pragma unroll
        for (int i = tid; i < 32*16; i += 256) {
            const int r  = i >> 4;
            const int c4 = (i & 15) << 2;
            float4 v = *(const float4*)&qbase[(size_t)r * DD + c4];
            v.x *= 0.125f; v.y *= 0.125f; v.z *= 0.125f; v.w *= 0.125f;
            *(float4*)&Qs[r][c4] = v;
        }
    }

    float pqx[4], pqy[4];
    #pragma unroll
    for (int i = 0; i < 4; i++) {
        const int qg = q0 + w4 + i;
        pqx[i] = pos[(size_t)(a*TT + qg)*2 + 0];
        pqy[i] = pos[(size_t)(a*TT + qg)*2 + 1];
    }
    float mrow[4] = {-1e30f, -1e30f, -1e30f, -1e30f};
    float lrow[4] = {0.f, 0.f, 0.f, 0.f};
    ull   o2[4]   = {0ull, 0ull, 0ull, 0ull};

    int jlo = q0 - tw;       if (jlo < 0)      jlo = 0;
    int jhi = q0 + 31 + tw;  if (jhi > TT - 1) jhi = TT - 1;

    // chunk-index range for this split
    const int nch = ((jhi - jlo) >> 5) + 1;
    const int ci0 = (nch * s) / NSPL;
    const int ci1 = (nch * (s + 1)) / NSPL;

    for (int ci = ci0; ci < ci1; ci++) {
        const int c0 = jlo + (ci << 5);
        const int cn = min(32, jhi - c0 + 1);

        __syncthreads();
        {
            const float* kbase = g_k + (size_t)(a*TT + c0) * DD + h*HDIM;
            const float* vbase = g_v + (size_t)(a*TT + c0) * DD + h*HDIM;
            #pragma unroll
            for (int i = tid; i < 32*16; i += 256) {
                const int r  = i >> 4;
                const int c4 = (i & 15) << 2;
                if (r < cn) {
                    *(float4*)&Ks[r][c4] = *(const float4*)&kbase[(size_t)r * DD + c4];
                    *(float4*)&Vs[r][c4] = *(const float4*)&vbase[(size_t)r * DD + c4];
                } else {
                    const float4 z = {0.f, 0.f, 0.f, 0.f};
                    *(float4*)&Vs[r][c4] = z;
                }
            }
        }
        __syncthreads();

        const int  jg   = c0 + lane;
        const bool lval = (lane < cn);
        float pkx = 0.f, pky = 0.f;
        if (lval) {
            pkx = pos[(size_t)(a*TT + jg)*2 + 0];
            pky = pos[(size_t)(a*TT + jg)*2 + 1];
        }

        ull s2[4] = {0ull, 0ull, 0ull, 0ull};
        #pragma unroll
        for (int d4 = 0; d4 < 16; d4++) {
            ulonglong2 kk = *(const ulonglong2*)&Ks[lane][d4 << 2];
            #pragma unroll
            for (int i = 0; i < 4; i++) {
                ulonglong2 qq = *(const ulonglong2*)&Qs[w4 + i][d4 << 2];
                fma2(s2[i], qq.x, kk.x);
                fma2(s2[i], qq.y, kk.y);
            }
        }

        float p_reg[4], sf[4];
        #pragma unroll
        for (int i = 0; i < 4; i++) {
            float2 sv = unpack2(s2[i]);
            float  sc = sv.x + sv.y;

            const int qg = q0 + w4 + i;
            int dt = qg - jg; dt = dt < 0 ? -dt : dt;
            const float dx = pqx[i] - pkx;
            const float dy = pqy[i] - pky;
            const bool ok = lval && (dt <= tw) && (dx*dx + dy*dy <= md2);
            if (!ok) sc = -1e30f;

            float cm = sc;
            #pragma unroll
            for (int off = 16; off; off >>= 1)
                cm = fmaxf(cm, __shfl_xor_sync(0xffffffffu, cm, off));
            const float mi = fmaxf(mrow[i], cm);

            float pp = ok ? __expf(sc - mi) : 0.f;
            float cs = pp;
            #pragma unroll
            for (int off = 16; off; off >>= 1)
                cs += __shfl_xor_sync(0xffffffffu, cs, off);

            sf[i]    = __expf(mrow[i] - mi);
            lrow[i]  = lrow[i] * sf[i] + cs;
            mrow[i]  = mi;
            p_reg[i] = pp;
        }

        #pragma unroll
        for (int i = 0; i < 4; i++)
            o2[i] = mul2(o2[i], dup2(sf[i]));

        #pragma unroll
        for (int j = 0; j < 32; j++) {
            ull vv = *(const ull*)&Vs[j][lane << 1];
            #pragma unroll
            for (int i = 0; i < 4; i++) {
                float pj = __shfl_sync(0xffffffffu, p_reg[i], j);
                fma2(o2[i], dup2(pj), vv);
            }
        }
    }

    // write partials (unnormalized o; per-query m, l)
    #pragma unroll
    for (int i = 0; i < 4; i++) {
        const int qg   = q0 + w4 + i;
        const int qi   = (a*HH + h)*TT + qg;
        const int base = s*AHT + qi;
        float2 ov = unpack2(o2[i]);
        *(float2*)&g_po[(size_t)base * HDIM + (lane << 1)] = ov;
        if (lane == 0) {
            g_pm[base] = mrow[i];
            g_pl[base] = lrow[i];
        }
    }
}

// ---------------------------------------------------------------------------
// Combine partials -> g_ctx.  One thread per (query, dim-pair).
// ---------------------------------------------------------------------------
__global__ __launch_bounds__(256) void attn_combine()
{
    const int g  = blockIdx.x * 256 + threadIdx.x;     // [0, AHT*32)
    const int qi = g >> 5;
    const int dp = g & 31;

    const float m1 = g_pm[qi];
    const float m2 = g_pm[AHT + qi];
    const float l1 = g_pl[qi];
    const float l2 = g_pl[AHT + qi];
    const float m  = fmaxf(m1, m2);
    const float w1 = __expf(m1 - m);
    const float w2 = __expf(m2 - m);
    const float inv = 1.f / (w1*l1 + w2*l2);

    const float2 o1 = *(const float2*)&g_po[(size_t)qi * HDIM + (dp << 1)];
    const float2 o2 = *(const float2*)&g_po[(size_t)(AHT + qi) * HDIM + (dp << 1)];
    float2 r;
    r.x = (w1*o1.x + w2*o2.x) * inv;
    r.y = (w1*o1.y + w2*o2.y) * inv;

    const int a = qi / (HH*TT);
    const int h = (qi / TT) % HH;
    const int t = qi % TT;
    *(float2*)&g_ctx[((size_t)(a*TT + t)) * DD + h*HDIM + (dp << 1)] = r;
}

// ---------------------------------------------------------------------------
// Launch
// ---------------------------------------------------------------------------
extern "C" void kernel_launch(void* const* d_in, const int* in_sizes, int n_in,
                              void* d_out, int out_size)
{
    const float* feat = (const float*)d_in[0];
    const float* posn = (const float*)d_in[1];
    const float* Wq   = (const float*)d_in[2];
    const float* bq   = (const float*)d_in[3];
    const float* Wk   = (const float*)d_in[4];
    const float* bk   = (const float*)d_in[5];
    const float* Wv   = (const float*)d_in[6];
    const float* bv   = (const float*)d_in[7];
    const float* Wo   = (const float*)d_in[8];
    const float* bo   = (const float*)d_in[9];
    const int*   pmd  = (const int*)d_in[10];
    const int*   ptw  = (const int*)d_in[11];

    void *pq, *pk, *pv, *pctx;
    cudaGetSymbolAddress(&pq,   g_q);
    cudaGetSymbolAddress(&pk,   g_k);
    cudaGetSymbolAddress(&pv,   g_v);
    cudaGetSymbolAddress(&pctx, g_ctx);

    gemm_qkv<<<dim3(AT/128, DD/128, 3), 256>>>(
        feat, Wq, Wk, Wv, bq, bk, bv, (float*)pq, (float*)pk, (float*)pv);

    attn_part<<<dim3((TT/32)*NSPL, HH, AA), 256>>>(posn, pmd, ptw);
    attn_combine<<<(AHT*32)/256, 256>>>();

    gemm_single<<<dim3(AT/128, DD/128, 1), 256>>>(
        (const float*)pctx, Wo, bo, (float*)d_out);
}

// round 12
// speedup vs baseline: 1.0690x; 1.0690x over previous
#include <cuda_runtime.h>

#define AA   64
#define TT   512
#define DD   256
#define HH   4
#define HDIM 64
#define AT   (AA*TT)

typedef unsigned long long ull;

// Scratch (allocation-free)
__device__ float g_q[AT*DD];
__device__ float g_k[AT*DD];
__device__ float g_v[AT*DD];
__device__ float g_ctx[AT*DD];

// ---------------------------------------------------------------------------
// f32x2 packed-math helpers (base-sm_103 FFMA2 path — ptxas never auto-emits)
// ---------------------------------------------------------------------------
__device__ __forceinline__ ull dup2(float x) {
    ull r;
    asm("mov.b64 %0, {%1, %1};" : "=l"(r) : "r"(__float_as_uint(x)));
    return r;
}
__device__ __forceinline__ void fma2(ull &d, ull a, ull b) {
    asm("fma.rn.f32x2 %0, %1, %2, %0;" : "+l"(d) : "l"(a), "l"(b));
}
__device__ __forceinline__ ull mul2(ull a, ull b) {
    ull r;
    asm("mul.rn.f32x2 %0, %1, %2;" : "=l"(r) : "l"(a), "l"(b));
    return r;
}
__device__ __forceinline__ float2 unpack2(ull v) {
    float2 f;
    asm("mov.b64 {%0, %1}, %2;" : "=f"(f.x), "=f"(f.y) : "l"(v));
    return f;
}

// ---------------------------------------------------------------------------
// GEMM (exact R8): BM=BN=128, BK=16, double-buffered, FFMA2.
// ---------------------------------------------------------------------------
__device__ __forceinline__ void gemm_tile(
    const float (* __restrict__ Ak)[132], const float (* __restrict__ Bk)[132],
    int tx, int ty, ull acc[8][4])
{
    #pragma unroll
    for (int k = 0; k < 16; k++) {
        const float4     a0 = *(const float4*)&Ak[k][ty << 2];
        const float4     a1 = *(const float4*)&Ak[k][64 + (ty << 2)];
        const ulonglong2 b0 = *(const ulonglong2*)&Bk[k][tx << 2];
        const ulonglong2 b1 = *(const ulonglong2*)&Bk[k][64 + (tx << 2)];
        ull am[8] = { dup2(a0.x), dup2(a0.y), dup2(a0.z), dup2(a0.w),
                      dup2(a1.x), dup2(a1.y), dup2(a1.z), dup2(a1.w) };
        #pragma unroll
        for (int mi = 0; mi < 8; mi++) {
            fma2(acc[mi][0], am[mi], b0.x);
            fma2(acc[mi][1], am[mi], b0.y);
            fma2(acc[mi][2], am[mi], b1.x);
            fma2(acc[mi][3], am[mi], b1.y);
        }
    }
}

__device__ __forceinline__ void gemm_body(
    const float* __restrict__ X, const float* __restrict__ W,
    const float* __restrict__ bias, float* __restrict__ Y,
    int m0, int n0)
{
    __shared__ float As[2][16][132];
    __shared__ float Bs[2][16][132];

    const int tid = threadIdx.x;
    const int tx  = tid & 15;
    const int ty  = tid >> 4;
    const int lr  = tid >> 2;
    const int lc  = (tid & 3) << 2;

    ull acc[8][4];
    #pragma unroll
    for (int i = 0; i < 8; i++)
        #pragma unroll
        for (int j = 0; j < 4; j++) acc[i][j] = 0ull;

    const float* xp0 = &X[(size_t)(m0 + lr)      * DD + lc];
    const float* xp1 = &X[(size_t)(m0 + 64 + lr) * DD + lc];
    const float* wp0 = &W[(size_t)(n0 + lr)      * DD + lc];
    const float* wp1 = &W[(size_t)(n0 + 64 + lr) * DD + lc];

    {
        float4 x0 = *(const float4*)(xp0);
        float4 x1 = *(const float4*)(xp1);
        float4 w0 = *(const float4*)(wp0);
        float4 w1 = *(const float4*)(wp1);
        As[0][lc+0][lr] = x0.x; As[0][lc+1][lr] = x0.y; As[0][lc+2][lr] = x0.z; As[0][lc+3][lr] = x0.w;
        As[0][lc+0][64+lr] = x1.x; As[0][lc+1][64+lr] = x1.y; As[0][lc+2][64+lr] = x1.z; As[0][lc+3][64+lr] = x1.w;
        Bs[0][lc+0][lr] = w0.x; Bs[0][lc+1][lr] = w0.y; Bs[0][lc+2][lr] = w0.z; Bs[0][lc+3][lr] = w0.w;
        Bs[0][lc+0][64+lr] = w1.x; Bs[0][lc+1][64+lr] = w1.y; Bs[0][lc+2][64+lr] = w1.z; Bs[0][lc+3][64+lr] = w1.w;
    }
    __syncthreads();

    int p = 0;
    for (int k0 = 16; k0 < 256; k0 += 16) {
        float4 x0 = *(const float4*)(xp0 + k0);
        float4 x1 = *(const float4*)(xp1 + k0);
        float4 w0 = *(const float4*)(wp0 + k0);
        float4 w1 = *(const float4*)(wp1 + k0);

        gemm_tile(As[p], Bs[p], tx, ty, acc);

        const int q = p ^ 1;
        As[q][lc+0][lr] = x0.x; As[q][lc+1][lr] = x0.y; As[q][lc+2][lr] = x0.z; As[q][lc+3][lr] = x0.w;
        As[q][lc+0][64+lr] = x1.x; As[q][lc+1][64+lr] = x1.y; As[q][lc+2][64+lr] = x1.z; As[q][lc+3][64+lr] = x1.w;
        Bs[q][lc+0][lr] = w0.x; Bs[q][lc+1][lr] = w0.y; Bs[q][lc+2][lr] = w0.z; Bs[q][lc+3][lr] = w0.w;
        Bs[q][lc+0][64+lr] = w1.x; Bs[q][lc+1][64+lr] = w1.y; Bs[q][lc+2][64+lr] = w1.z; Bs[q][lc+3][64+lr] = w1.w;
        __syncthreads();
        p = q;
    }
    gemm_tile(As[p], Bs[p], tx, ty, acc);

    float4 bv0 = *(const float4*)&bias[n0 + (tx << 2)];
    float4 bv1 = *(const float4*)&bias[n0 + 64 + (tx << 2)];
    #pragma unroll
    for (int mi = 0; mi < 8; mi++) {
        const int m = m0 + ((mi < 4) ? ((ty << 2) + mi) : (64 + (ty << 2) + mi - 4));
        float2 p0 = unpack2(acc[mi][0]);
        float2 p1 = unpack2(acc[mi][1]);
        float4 r0 = { p0.x + bv0.x, p0.y + bv0.y, p1.x + bv0.z, p1.y + bv0.w };
        *(float4*)&Y[(size_t)m * DD + n0 + (tx << 2)] = r0;
        float2 p2 = unpack2(acc[mi][2]);
        float2 p3 = unpack2(acc[mi][3]);
        float4 r1 = { p2.x + bv1.x, p2.y + bv1.y, p3.x + bv1.z, p3.y + bv1.w };
        *(float4*)&Y[(size_t)m * DD + n0 + 64 + (tx << 2)] = r1;
    }
}

__global__ __launch_bounds__(256, 2) void gemm_qkv(
    const float* __restrict__ X,
    const float* __restrict__ Wq, const float* __restrict__ Wk, const float* __restrict__ Wv,
    const float* __restrict__ bq, const float* __restrict__ bk, const float* __restrict__ bv,
    float* __restrict__ Yq, float* __restrict__ Yk, float* __restrict__ Yv)
{
    const int z = blockIdx.z;
    const float* W = (z == 0) ? Wq : (z == 1) ? Wk : Wv;
    const float* b = (z == 0) ? bq : (z == 1) ? bk : bv;
    float*       Y = (z == 0) ? Yq : (z == 1) ? Yk : Yv;
    gemm_body(X, W, b, Y, blockIdx.x * 128, blockIdx.y * 128);
}

__global__ __launch_bounds__(256, 2) void gemm_single(
    const float* __restrict__ X, const float* __restrict__ W,
    const float* __restrict__ bias, float* __restrict__ Y)
{
    gemm_body(X, W, bias, Y, blockIdx.x * 128, blockIdx.y * 128);
}

// ---------------------------------------------------------------------------
// Banded sparse attention — EXACT R4/R8 compute core; ONLY change vs the
// 594.8us best: __launch_bounds__(256, 3) -> 3 CTAs/SM (24 warps resident)
// to cover LDS/shfl/MUFU latency that 16 warps could not hide.
// ---------------------------------------------------------------------------
__global__ __launch_bounds__(256, 3) void attn_banded(
    const float* __restrict__ pos,
    const int* __restrict__ p_md, const int* __restrict__ p_tw)
{
    __shared__ float Qs[32][68];
    __shared__ float Ks[32][68];
    __shared__ float Vs[32][68];

    const int a    = blockIdx.z;
    const int h    = blockIdx.y;
    const int q0   = blockIdx.x * 32;
    const int tid  = threadIdx.x;
    const int w    = tid >> 5;
    const int lane = tid & 31;
    const int w4   = w << 2;

    const int   tw  = *p_tw;
    const float mdf = (float)(*p_md);
    const float md2 = mdf * mdf;

    {
        const float* qbase = g_q + (size_t)(a*TT + q0) * DD + h*HDIM;
        #pragma unroll
        for (int i = tid; i < 32*16; i += 256) {
            const int r  = i >> 4;
            const int c4 = (i & 15) << 2;
            float4 v = *(const float4*)&qbase[(size_t)r * DD + c4];
            v.x *= 0.125f; v.y *= 0.125f; v.z *= 0.125f; v.w *= 0.125f;
            *(float4*)&Qs[r][c4] = v;
        }
    }

    float pqx[4], pqy[4];
    #pragma unroll
    for (int i = 0; i < 4; i++) {
        const int qg = q0 + w4 + i;
        pqx[i] = pos[(size_t)(a*TT + qg)*2 + 0];
        pqy[i] = pos[(size_t)(a*TT + qg)*2 + 1];
    }
    float mrow[4] = {-1e30f, -1e30f, -1e30f, -1e30f};
    float lrow[4] = {0.f, 0.f, 0.f, 0.f};
    ull   o2[4]   = {0ull, 0ull, 0ull, 0ull};

    int jlo = q0 - tw;       if (jlo < 0)      jlo = 0;
    int jhi = q0 + 31 + tw;  if (jhi > TT - 1) jhi = TT - 1;

    for (int c0 = jlo; c0 <= jhi; c0 += 32) {
        const int cn = min(32, jhi - c0 + 1);

        __syncthreads();
        {
            const float* kbase = g_k + (size_t)(a*TT + c0) * DD + h*HDIM;
            const float* vbase = g_v + (size_t)(a*TT + c0) * DD + h*HDIM;
            #pragma unroll
            for (int i = tid; i < 32*16; i += 256) {
                const int r  = i >> 4;
                const int c4 = (i & 15) << 2;
                if (r < cn) {
                    *(float4*)&Ks[r][c4] = *(const float4*)&kbase[(size_t)r * DD + c4];
                    *(float4*)&Vs[r][c4] = *(const float4*)&vbase[(size_t)r * DD + c4];
                } else {
                    const float4 z = {0.f, 0.f, 0.f, 0.f};
                    *(float4*)&Vs[r][c4] = z;
                }
            }
        }
        __syncthreads();

        const int  jg   = c0 + lane;
        const bool lval = (lane < cn);
        float pkx = 0.f, pky = 0.f;
        if (lval) {
            pkx = pos[(size_t)(a*TT + jg)*2 + 0];
            pky = pos[(size_t)(a*TT + jg)*2 + 1];
        }

        ull s2[4] = {0ull, 0ull, 0ull, 0ull};
        #pragma unroll
        for (int d4 = 0; d4 < 16; d4++) {
            ulonglong2 kk = *(const ulonglong2*)&Ks[lane][d4 << 2];
            #pragma unroll
            for (int i = 0; i < 4; i++) {
                ulonglong2 qq = *(const ulonglong2*)&Qs[w4 + i][d4 << 2];
                fma2(s2[i], qq.x, kk.x);
                fma2(s2[i], qq.y, kk.y);
            }
        }

        float p_reg[4], sf[4];
        #pragma unroll
        for (int i = 0; i < 4; i++) {
            float2 sv = unpack2(s2[i]);
            float  s  = sv.x + sv.y;

            const int qg = q0 + w4 + i;
            int dt = qg - jg; dt = dt < 0 ? -dt : dt;
            const float dx = pqx[i] - pkx;
            const float dy = pqy[i] - pky;
            const bool ok = lval && (dt <= tw) && (dx*dx + dy*dy <= md2);
            if (!ok) s = -1e30f;

            float cm = s;
            #pragma unroll
            for (int off = 16; off; off >>= 1)
                cm = fmaxf(cm, __shfl_xor_sync(0xffffffffu, cm, off));
            const float mi = fmaxf(mrow[i], cm);

            float p = ok ? __expf(s - mi) : 0.f;
            float cs = p;
            #pragma unroll
            for (int off = 16; off; off >>= 1)
                cs += __shfl_xor_sync(0xffffffffu, cs, off);

            sf[i]    = __expf(mrow[i] - mi);
            lrow[i]  = lrow[i] * sf[i] + cs;
            mrow[i]  = mi;
            p_reg[i] = p;
        }

        #pragma unroll
        for (int i = 0; i < 4; i++)
            o2[i] = mul2(o2[i], dup2(sf[i]));

        #pragma unroll
        for (int j = 0; j < 32; j++) {
            ull vv = *(const ull*)&Vs[j][lane << 1];
            #pragma unroll
            for (int i = 0; i < 4; i++) {
                float pj = __shfl_sync(0xffffffffu, p_reg[i], j);
                fma2(o2[i], dup2(pj), vv);
            }
        }
    }

    #pragma unroll
    for (int i = 0; i < 4; i++) {
        const int   qg  = q0 + w4 + i;
        const float inv = 1.f / lrow[i];
        float2 ov = unpack2(o2[i]);
        float2 r;
        r.x = ov.x * inv;
        r.y = ov.y * inv;
        *(float2*)&g_ctx[(size_t)(a*TT + qg) * DD + h*HDIM + (lane << 1)] = r;
    }
}

// ---------------------------------------------------------------------------
// Launch
// ---------------------------------------------------------------------------
extern "C" void kernel_launch(void* const* d_in, const int* in_sizes, int n_in,
                              void* d_out, int out_size)
{
    const float* feat = (const float*)d_in[0];
    const float* posn = (const float*)d_in[1];
    const float* Wq   = (const float*)d_in[2];
    const float* bq   = (const float*)d_in[3];
    const float* Wk   = (const float*)d_in[4];
    const float* bk   = (const float*)d_in[5];
    const float* Wv   = (const float*)d_in[6];
    const float* bv   = (const float*)d_in[7];
    const float* Wo   = (const float*)d_in[8];
    const float* bo   = (const float*)d_in[9];
    const int*   pmd  = (const int*)d_in[10];
    const int*   ptw  = (const int*)d_in[11];

    void *pq, *pk, *pv, *pctx;
    cudaGetSymbolAddress(&pq,   g_q);
    cudaGetSymbolAddress(&pk,   g_k);
    cudaGetSymbolAddress(&pv,   g_v);
    cudaGetSymbolAddress(&pctx, g_ctx);

    gemm_qkv<<<dim3(AT/128, DD/128, 3), 256>>>(
        feat, Wq, Wk, Wv, bq, bk, bv, (float*)pq, (float*)pk, (float*)pv);

    attn_banded<<<dim3(TT/32, HH, AA), 256>>>(posn, pmd, ptw);

    gemm_single<<<dim3(AT/128, DD/128, 1), 256>>>(
        (const float*)pctx, Wo, bo, (float*)d_out);
}